// round 3
// baseline (speedup 1.0000x reference)
#include <cuda_runtime.h>
#include <cuda_bf16.h>

// LSTM_1279900254644: 2-layer LSTM, B=512, L=1000, H=128, scalar in/out per step.
// Batch-parallel persistent blocks; weights streamed from L2 each step (L2-resident).
// Packed f32x2 FMA for the gate mat-vecs.

#define B_DIM 512
#define L_DIM 1000
#define H_DIM 128
#define G_DIM 512      // 4*H
#define MB    6        // batch tile per block
#define NBLK  86       // ceil(512/6)
#define BLK_T 512      // threads per block (== G_DIM)
#define NK4   32       // 128 K-values / 4

// Packed weight scratch: [k4][row] float4, one float4 = W[row][4k4..4k4+3]
__device__ float4 g_w1 [NK4 * G_DIM];   // W_hh1
__device__ float4 g_w2i[NK4 * G_DIM];   // W_ih2
__device__ float4 g_w2h[NK4 * G_DIM];   // W_hh2

__device__ __forceinline__ unsigned long long pk(float x, float y) {
    unsigned long long r;
    asm("mov.b64 %0, {%1,%2};" : "=l"(r) : "f"(x), "f"(y));
    return r;
}
__device__ __forceinline__ void ffma2(unsigned long long& d,
                                      unsigned long long a, unsigned long long b) {
    asm("fma.rn.f32x2 %0, %1, %2, %0;" : "+l"(d) : "l"(a), "l"(b));
}
__device__ __forceinline__ float pksum(unsigned long long v) {
    float a, b;
    asm("mov.b64 {%0,%1}, %2;" : "=f"(a), "=f"(b) : "l"(v));
    return a + b;
}
__device__ __forceinline__ float sigf(float x) {
    return __fdividef(1.f, 1.f + __expf(-x));
}
__device__ __forceinline__ float tanh_fast(float x) {
    // tanh(x) = 1 - 2/(exp(2x)+1); __expf handles overflow to +inf cleanly.
    return 1.f - __fdividef(2.f, __expf(2.f * x) + 1.f);
}

__global__ void pack_weights(const float* __restrict__ w1,
                             const float* __restrict__ w2i,
                             const float* __restrict__ w2h) {
    int idx = blockIdx.x * blockDim.x + threadIdx.x;   // over 3 * 32 * 512 float4s
    if (idx >= 3 * NK4 * G_DIM) return;
    int mat = idx / (NK4 * G_DIM);
    int rem = idx % (NK4 * G_DIM);
    int k4  = rem / G_DIM;
    int r   = rem % G_DIM;
    const float* src = (mat == 0) ? w1 : (mat == 1) ? w2i : w2h;
    float4 v;
    v.x = src[r * H_DIM + 4 * k4 + 0];
    v.y = src[r * H_DIM + 4 * k4 + 1];
    v.z = src[r * H_DIM + 4 * k4 + 2];
    v.w = src[r * H_DIM + 4 * k4 + 3];
    if (mat == 0)      g_w1 [rem] = v;
    else if (mat == 1) g_w2i[rem] = v;
    else               g_w2h[rem] = v;
}

__global__ __launch_bounds__(BLK_T, 1)
void lstm_main(const float* __restrict__ y,
               const float* __restrict__ Wih1,
               const float* __restrict__ bih1,
               const float* __restrict__ bhh1,
               const float* __restrict__ bih2,
               const float* __restrict__ bhh2,
               const float* __restrict__ Wlin,
               const float* __restrict__ blin,
               float* __restrict__ out) {
    const int r  = threadIdx.x;           // gate row 0..511
    const int b0 = blockIdx.x * MB;

    __shared__ float h1s[MB][H_DIM];
    __shared__ float h2s[MB][H_DIM];
    __shared__ float gs [MB][G_DIM];
    __shared__ float xs [MB];
    __shared__ float red[MB][4];

    // zero state
    for (int i = r; i < MB * H_DIM; i += BLK_T) {
        (&h1s[0][0])[i] = 0.f;
        (&h2s[0][0])[i] = 0.f;
    }
    float c1r[MB], c2r[MB];
    #pragma unroll
    for (int m = 0; m < MB; ++m) { c1r[m] = 0.f; c2r[m] = 0.f; }

    const float wih1_r  = Wih1[r];
    const float bias1_r = bih1[r] + bhh1[r];
    const float bias2_r = bih2[r] + bhh2[r];
    const float wlin_r  = (r < H_DIM) ? Wlin[r] : 0.f;
    const float blin0   = blin[0];

    if (r < MB) {
        int b = b0 + r;
        xs[r] = (b < B_DIM) ? y[b * L_DIM + 0] : 0.f;
    }
    __syncthreads();

    for (int t = 0; t < L_DIM; ++t) {
        // ---- stage A: layer-1 gates: g1 = x*Wih1 + b + h1 @ Whh1^T ----
        unsigned long long acc[MB];
        #pragma unroll
        for (int m = 0; m < MB; ++m)
            acc[m] = pk(fmaf(xs[m], wih1_r, bias1_r), 0.f);

        #pragma unroll 8
        for (int k4 = 0; k4 < NK4; ++k4) {
            float4 w = g_w1[k4 * G_DIM + r];
            unsigned long long w01 = pk(w.x, w.y);
            unsigned long long w23 = pk(w.z, w.w);
            #pragma unroll
            for (int m = 0; m < MB; ++m) {
                float4 hv = *reinterpret_cast<const float4*>(&h1s[m][4 * k4]);
                ffma2(acc[m], w01, pk(hv.x, hv.y));
                ffma2(acc[m], w23, pk(hv.z, hv.w));
            }
        }
        #pragma unroll
        for (int m = 0; m < MB; ++m) gs[m][r] = pksum(acc[m]);
        __syncthreads();

        // ---- stage B: layer-1 cell update (threads r < H), x prefetch (tail threads) ----
        if (r < H_DIM) {
            #pragma unroll
            for (int m = 0; m < MB; ++m) {
                float gi = gs[m][r];
                float gf = gs[m][r + 128];
                float gg = gs[m][r + 256];
                float go = gs[m][r + 384];
                float i = sigf(gi), f = sigf(gf), g = tanh_fast(gg), o = sigf(go);
                float c = f * c1r[m] + i * g;
                c1r[m] = c;
                h1s[m][r] = o * tanh_fast(c);
            }
        } else if (r >= BLK_T - MB) {
            int m = r - (BLK_T - MB);
            int b = b0 + m;
            xs[m] = (b < B_DIM && t + 1 < L_DIM) ? y[b * L_DIM + (t + 1)] : 0.f;
        }
        __syncthreads();

        // ---- stage C: layer-2 gates: g2 = h1 @ Wih2^T + b + h2 @ Whh2^T ----
        #pragma unroll
        for (int m = 0; m < MB; ++m)
            acc[m] = pk(bias2_r, 0.f);

        #pragma unroll 8
        for (int k4 = 0; k4 < NK4; ++k4) {
            float4 wi = g_w2i[k4 * G_DIM + r];
            float4 wh = g_w2h[k4 * G_DIM + r];
            unsigned long long wi01 = pk(wi.x, wi.y);
            unsigned long long wi23 = pk(wi.z, wi.w);
            unsigned long long wh01 = pk(wh.x, wh.y);
            unsigned long long wh23 = pk(wh.z, wh.w);
            #pragma unroll
            for (int m = 0; m < MB; ++m) {
                float4 h1v = *reinterpret_cast<const float4*>(&h1s[m][4 * k4]);
                float4 h2v = *reinterpret_cast<const float4*>(&h2s[m][4 * k4]);
                ffma2(acc[m], wi01, pk(h1v.x, h1v.y));
                ffma2(acc[m], wi23, pk(h1v.z, h1v.w));
                ffma2(acc[m], wh01, pk(h2v.x, h2v.y));
                ffma2(acc[m], wh23, pk(h2v.z, h2v.w));
            }
        }
        #pragma unroll
        for (int m = 0; m < MB; ++m) gs[m][r] = pksum(acc[m]);
        __syncthreads();

        // ---- stage D: layer-2 cell update + output dot partials (threads r < H) ----
        if (r < H_DIM) {
            #pragma unroll
            for (int m = 0; m < MB; ++m) {
                float gi = gs[m][r];
                float gf = gs[m][r + 128];
                float gg = gs[m][r + 256];
                float go = gs[m][r + 384];
                float i = sigf(gi), f = sigf(gf), g = tanh_fast(gg), o = sigf(go);
                float c = f * c2r[m] + i * g;
                c2r[m] = c;
                float hn = o * tanh_fast(c);
                h2s[m][r] = hn;
                float p = hn * wlin_r;
                #pragma unroll
                for (int off = 16; off > 0; off >>= 1)
                    p += __shfl_down_sync(0xffffffffu, p, off);
                if ((r & 31) == 0) red[m][r >> 5] = p;
            }
        }
        __syncthreads();

        // ---- stage E: final reduce + store ----
        if (r < MB) {
            int b = b0 + r;
            if (b < B_DIM)
                out[b * L_DIM + t] =
                    red[r][0] + red[r][1] + red[r][2] + red[r][3] + blin0;
        }
        __syncthreads();
    }
}

extern "C" void kernel_launch(void* const* d_in, const int* in_sizes, int n_in,
                              void* d_out, int out_size) {
    const float* y    = (const float*)d_in[0];
    const float* Wih1 = (const float*)d_in[1];
    const float* Whh1 = (const float*)d_in[2];
    const float* bih1 = (const float*)d_in[3];
    const float* bhh1 = (const float*)d_in[4];
    const float* Wih2 = (const float*)d_in[5];
    const float* Whh2 = (const float*)d_in[6];
    const float* bih2 = (const float*)d_in[7];
    const float* bhh2 = (const float*)d_in[8];
    const float* Wlin = (const float*)d_in[9];
    const float* blin = (const float*)d_in[10];
    float* out = (float*)d_out;

    int pack_n = 3 * NK4 * G_DIM;
    pack_weights<<<(pack_n + 255) / 256, 256>>>(Whh1, Wih2, Whh2);
    lstm_main<<<NBLK, BLK_T>>>(y, Wih1, bih1, bhh1, bih2, bhh2, Wlin, blin, out);
}